// round 9
// baseline (speedup 1.0000x reference)
#include <cuda_runtime.h>
#include <math.h>

#define HH 1024
#define WW 1024
#define NB 2
#define KK 24   // number of SOCS kernels
#define KD 35   // kernel spatial size / cropped spectrum size
#define FC 17   // center offset: frequency f = index - 17
#define UH 9    // u-pairs per half (18 total)
#define NS 128  // x-sample points (x = 8j)
#define NDV 69  // dv = -34..34

// ---------------- scratch (static __device__, no allocation) ----------------
__device__ float2 g_cs[1024];                 // e^{+2pi i t/1024}
__device__ float2 g_T[NB][KD][HH];            // row DFT, transposed (j2-major)
__device__ float2 g_spec[NB][KD][KD];         // cropped spectrum (1/(H*W) folded)
__device__ float2 g_Rs[NB][2][KK][KD][NS];    // R at 128 x-samples
__device__ float2 g_Gp[8][NB][2][KD][NS];     // per-k-group partial Gram at samples
__device__ float2 g_G[NB][2][KD][NDV];        // spectral Gram G[du][dv]
__device__ float2 g_D[NB][2][KD][WW];         // cross-spectral density over du

// ---------------- f32x2 packed helpers (Blackwell) ----------------
__device__ __forceinline__ unsigned long long pk2(float lo, float hi) {
    unsigned long long r;
    asm("mov.b64 %0, {%1, %2};" : "=l"(r) : "f"(lo), "f"(hi));
    return r;
}
__device__ __forceinline__ unsigned long long fma2(unsigned long long a, unsigned long long b, unsigned long long c) {
    unsigned long long d;
    asm("fma.rn.f32x2 %0, %1, %2, %3;" : "=l"(d) : "l"(a), "l"(b), "l"(c));
    return d;
}
__device__ __forceinline__ void upk2(unsigned long long v, float& lo, float& hi) {
    asm("mov.b64 {%0, %1}, %2;" : "=f"(lo), "=f"(hi) : "l"(v));
}

// ---------------- twiddle table ----------------
__global__ void k_table() {
    int t = threadIdx.x;
    float s, c;
    sincospif((float)t / 512.0f, &s, &c);     // angle = 2*pi*t/1024
    g_cs[t] = make_float2(c, s);
}

// ---------------- stage 1: fused avepool3+sigmoid + row DFT, 4 rows/block ----------------
__global__ void __launch_bounds__(256) k_rowdft(const float* __restrict__ mask) {
    __shared__ float raw[6][WW];
    __shared__ float m_s[4][WW];
    int yb = blockIdx.x;                      // 256 blocks of 4 rows
    int n  = blockIdx.y;
    int tid = threadIdx.x;
    const float* base = mask + (size_t)n * HH * WW;
    #pragma unroll
    for (int j = 0; j < 6; j++) {
        int gy = yb*4 - 1 + j;
        for (int x = tid; x < WW; x += 256)
            raw[j][x] = (gy >= 0 && gy < HH) ? base[(size_t)gy * WW + x] : 0.f;
    }
    __syncthreads();
    for (int x = tid; x < WW; x += 256) {
        float r0 = raw[0][x], r1 = raw[1][x], r2 = raw[2][x];
        float r3 = raw[3][x], r4 = raw[4][x], r5 = raw[5][x];
        raw[0][x] = r0 + r1 + r2;
        raw[1][x] = r1 + r2 + r3;
        raw[2][x] = r2 + r3 + r4;
        raw[3][x] = r3 + r4 + r5;
    }
    __syncthreads();
    for (int x = tid; x < WW; x += 256) {
        #pragma unroll
        for (int yy = 0; yy < 4; yy++) {
            float s = raw[yy][x];
            if (x > 0)    s += raw[yy][x-1];
            if (x < WW-1) s += raw[yy][x+1];
            float p = s * (1.0f/9.0f);
            m_s[yy][x] = 1.0f / (1.0f + expf(-4.0f * (p - 0.5f)));
        }
    }
    __syncthreads();
    int warp = tid >> 5, lane = tid & 31;
    for (int j2 = warp; j2 < KD; j2 += 8) {
        int a = FC - j2;                      // e^{-2pi i (j2-17) x/N} = cs[(a*x) mod N]
        float2 t  = g_cs[(a * lane) & 1023];
        float2 st = g_cs[(a * 32)   & 1023];
        unsigned long long acc[4] = {0ull, 0ull, 0ull, 0ull};
        for (int i = 0; i < 32; i++) {
            int x = lane + 32*i;
            unsigned long long t2 = pk2(t.x, t.y);
            #pragma unroll
            for (int yy = 0; yy < 4; yy++) {
                float mv = m_s[yy][x];
                acc[yy] = fma2(pk2(mv, mv), t2, acc[yy]);
            }
            float tx = t.x*st.x - t.y*st.y;
            float ty = t.x*st.y + t.y*st.x;
            t = make_float2(tx, ty);
        }
        #pragma unroll
        for (int yy = 0; yy < 4; yy++) {
            float ar, ai;
            upk2(acc[yy], ar, ai);
            for (int o = 16; o; o >>= 1) {
                ar += __shfl_xor_sync(0xffffffffu, ar, o);
                ai += __shfl_xor_sync(0xffffffffu, ai, o);
            }
            if (lane == 0) g_T[n][j2][yb*4 + yy] = make_float2(ar, ai);
        }
    }
}

// ---------------- stage 2: column DFT, one block per (j2,n) ----------------
__global__ void __launch_bounds__(256) k_coldft() {
    __shared__ float2 Ts[HH];
    int j2 = blockIdx.x, n = blockIdx.y;
    int tid = threadIdx.x;
    for (int i = tid; i < HH; i += 256) Ts[i] = g_T[n][j2][i];
    __syncthreads();
    int warp = tid >> 5, lane = tid & 31;
    const float norm = 1.0f / (1024.0f * 1024.0f);
    for (int j1 = warp; j1 < KD; j1 += 8) {
        int a = FC - j1;
        float2 t  = g_cs[(a * lane) & 1023];
        float2 st = g_cs[(a * 32)   & 1023];
        float ar = 0.f, ai = 0.f;
        for (int i = 0; i < 32; i++) {
            float2 T = Ts[lane + 32*i];
            ar += T.x*t.x - T.y*t.y;
            ai += T.x*t.y + T.y*t.x;
            float tx = t.x*st.x - t.y*st.y;
            float ty = t.x*st.y + t.y*st.x;
            t = make_float2(tx, ty);
        }
        for (int o = 16; o; o >>= 1) {
            ar += __shfl_xor_sync(0xffffffffu, ar, o);
            ai += __shfl_xor_sync(0xffffffffu, ai, o);
        }
        if (lane == 0) g_spec[n][j1][j2] = make_float2(ar * norm, ai * norm);
    }
}

// ---------------- stage 3: R at 128 x-samples (x = 8j) ----------------
__global__ void __launch_bounds__(128) k_R128(const float* __restrict__ fr, const float* __restrict__ fi,
                                              const float* __restrict__ dr, const float* __restrict__ di) {
    __shared__ float4 Bs[KD][UH + 1];         // (b0x, b1x, b0y, b1y) per (v, u2)
    int k = blockIdx.x;
    int z = blockIdx.y;                       // h(2) * nbr(4)
    int h = z & 1, nbr = z >> 1;
    int n = nbr >> 1, br = nbr & 1;
    int u2base = h * UH;
    int tid = threadIdx.x;
    const float* krp = (br == 0) ? fr : dr;
    const float* kip = (br == 0) ? fi : di;
    for (int i = tid; i < KD*UH; i += 128) {
        int uu = i / KD, v = i % KD;
        int u0 = 2*(u2base + uu), u1 = u0 + 1;
        float2 A0 = g_spec[n][u0][v];
        float Kr = krp[(k*KD + u0)*KD + v];
        float Ki = kip[(k*KD + u0)*KD + v];
        float b0x = A0.x*Kr - A0.y*Ki, b0y = A0.x*Ki + A0.y*Kr;
        float b1x = 0.f, b1y = 0.f;
        if (u1 < KD) {
            float2 A1 = g_spec[n][u1][v];
            float Kr1 = krp[(k*KD + u1)*KD + v];
            float Ki1 = kip[(k*KD + u1)*KD + v];
            b1x = A1.x*Kr1 - A1.y*Ki1; b1y = A1.x*Ki1 + A1.y*Kr1;
        }
        Bs[v][uu] = make_float4(b0x, b1x, b0y, b1y);
    }
    __syncthreads();
    int j = tid;                              // sample index, x = 8j
    float2 w = g_cs[(8 * j) & 1023];
    float2 t = make_float2(1.f, 0.f);
    unsigned long long aR[UH], aI[UH];
    #pragma unroll
    for (int uu = 0; uu < UH; uu++) { aR[uu] = 0ull; aI[uu] = 0ull; }
    #pragma unroll
    for (int v = 0; v < KD; v++) {
        unsigned long long pxx = pk2(t.x,  t.x);
        unsigned long long pyy = pk2(t.y,  t.y);
        unsigned long long nyy = pk2(-t.y, -t.y);
        #pragma unroll
        for (int uu = 0; uu < UH; uu++) {
            float4 b = Bs[v][uu];
            unsigned long long bx = pk2(b.x, b.y);
            unsigned long long by = pk2(b.z, b.w);
            aR[uu] = fma2(bx, pxx, aR[uu]);
            aR[uu] = fma2(by, nyy, aR[uu]);
            aI[uu] = fma2(bx, pyy, aI[uu]);
            aI[uu] = fma2(by, pxx, aI[uu]);
        }
        float tx = t.x*w.x - t.y*w.y;
        float ty = t.x*w.y + t.y*w.x;
        t = make_float2(tx, ty);
    }
    #pragma unroll
    for (int uu = 0; uu < UH; uu++) {
        int u0 = 2*(u2base + uu);
        float r0, r1, i0, i1;
        upk2(aR[uu], r0, r1);
        upk2(aI[uu], i0, i1);
        g_Rs[n][br][k][u0][j] = make_float2(r0, i0);
        if (u0 + 1 < KD) g_Rs[n][br][k][u0+1][j] = make_float2(r1, i1);
    }
}

// ---------------- stage 4: partial Gram at samples ----------------
template <int DU0, int DW>
__device__ __forceinline__ void gram_half(int n, int br, int kg, int j, const float* sp) {
    unsigned long long acc[DW];
    #pragma unroll
    for (int q = 0; q < DW; q++) acc[q] = 0ull;
    #pragma unroll 1
    for (int kk = 0; kk < 3; kk++) {
        int k = kg*3 + kk;
        float s = sp[k];
        float2 Ru[KD];
        #pragma unroll
        for (int u = 0; u < KD; u++) Ru[u] = g_Rs[n][br][k][u][j];
        #pragma unroll
        for (int u = 0; u < KD; u++) {
            float ax = s * Ru[u].x;
            float ay = s * Ru[u].y;
            unsigned long long axy  = pk2(ax, ay);
            unsigned long long ayxn = pk2(ay, -ax);
            #pragma unroll
            for (int q = 0; q < DW; q++) {
                if (DU0 + q <= u) {
                    float2 b = Ru[u - DU0 - q];
                    acc[q] = fma2(axy,  pk2(b.x, b.x), acc[q]);
                    acc[q] = fma2(ayxn, pk2(b.y, b.y), acc[q]);
                }
            }
        }
    }
    #pragma unroll
    for (int q = 0; q < DW; q++) {
        float rx, ry;
        upk2(acc[q], rx, ry);
        g_Gp[kg][n][br][DU0 + q][j] = make_float2(rx, ry);
    }
}

__global__ void __launch_bounds__(128) k_D1s(const float* __restrict__ fs, const float* __restrict__ ds) {
    int kg = blockIdx.x;                     // 8 k-groups of 3
    int z  = blockIdx.y;                     // nbr(4) * half(2)
    int nbr = z >> 1, half = z & 1;
    int n = nbr >> 1, br = nbr & 1;
    int j = threadIdx.x;                     // sample index
    const float* sp = (br == 0) ? fs : ds;
    if (half == 0) gram_half<0, 18>(n, br, kg, j, sp);
    else           gram_half<18, 17>(n, br, kg, j, sp);
}

// ---------------- stage 5: 128-pt inverse DFT -> G[du][dv] ----------------
// D_j = sum_dv G[dv] e^{+2pi i dv j/128}  ->  G[dv] = (1/128) sum_j D_j e^{-2pi i dv j/128}
__global__ void __launch_bounds__(128) k_G2() {
    __shared__ float2 Ds[NS];
    int du  = blockIdx.x;
    int nbr = blockIdx.y; int n = nbr >> 1, br = nbr & 1;
    int tid = threadIdx.x;
    {
        float sx = 0.f, sy = 0.f;
        #pragma unroll
        for (int kg = 0; kg < 8; kg++) {
            float2 t = g_Gp[kg][n][br][du][tid];
            sx += t.x; sy += t.y;
        }
        Ds[tid] = make_float2(sx, sy);
    }
    __syncthreads();
    if (tid < NDV) {
        int dv = tid - 34;
        float2 w = g_cs[(-8 * dv) & 1023];   // e^{-2pi i dv/128}
        float2 t = make_float2(1.f, 0.f);
        float gr = 0.f, gi = 0.f;
        #pragma unroll
        for (int j = 0; j < NS; j++) {
            float2 Dj = Ds[j];
            gr += Dj.x*t.x - Dj.y*t.y;
            gi += Dj.x*t.y + Dj.y*t.x;
            float tx = t.x*w.x - t.y*w.y;
            float ty = t.x*w.y + t.y*w.x;
            t = make_float2(tx, ty);
        }
        g_G[n][br][du][tid] = make_float2(gr * (1.0f/128.0f), gi * (1.0f/128.0f));
    }
}

// ---------------- stage 6: D[du][x] = sum_dv G[du][dv] e^{+2pi i dv x/1024} ----------------
__global__ void __launch_bounds__(256) k_Dsyn() {
    __shared__ float2 Gs[NDV];
    int du  = blockIdx.x;
    int nbr = blockIdx.y; int n = nbr >> 1, br = nbr & 1;
    int tid = threadIdx.x;
    if (tid < NDV) Gs[tid] = g_G[n][br][du][tid];
    __syncthreads();
    #pragma unroll
    for (int xi = 0; xi < 4; xi++) {
        int x = tid + 256*xi;
        float2 w = g_cs[x];                             // e^{+i 2pi x/1024}
        float2 t = g_cs[((-34) * x) & 1023];            // start at dv=-34
        float ar = 0.f, ai = 0.f;
        #pragma unroll
        for (int dvi = 0; dvi < NDV; dvi++) {
            float2 G = Gs[dvi];                         // warp-uniform broadcast
            ar += G.x*t.x - G.y*t.y;
            ai += G.x*t.y + G.y*t.x;
            float tx = t.x*w.x - t.y*w.y;
            float ty = t.x*w.y + t.y*w.x;
            t = make_float2(tx, ty);
        }
        g_D[n][br][du][x] = make_float2(ar, ai);
    }
}

// ---------------- stage 7: synthesis (du-pair packed, radix-2 in y) + outputs ----------------
__global__ void __launch_bounds__(256) k_final(float* __restrict__ out) {
    __shared__ unsigned long long twx[128][17];
    __shared__ unsigned long long twy[128][17];
    int xs = blockIdx.x;                     // 32-wide x strip
    int yq = blockIdx.y;                     // 0..3 (128 rows each, y in [0,512))
    int bz = blockIdx.z;                     // n(2) x br(2)
    int n = bz >> 1, br = bz & 1;
    int tid = threadIdx.x;
    for (int idx = tid; idx < 128*17; idx += 256) {
        int yp = idx / 17, p = idx % 17;
        int y = yq*128 + yp;
        float2 c0 = g_cs[((2*p+1) * y) & 1023];
        float2 c1 = g_cs[((2*p+2) * y) & 1023];
        twx[yp][p] = pk2(c0.x, c1.x);
        twy[yp][p] = pk2(c0.y, c1.y);
    }
    int lane = tid & 31, warp = tid >> 5;
    int x = xs*32 + lane;
    float D0 = g_D[n][br][0][x].x;           // D[0] is real
    unsigned long long dcx2[17], dcy2[17];
    #pragma unroll
    for (int p = 0; p < 17; p++) {
        float2 t0 = g_D[n][br][2*p+1][x];    // odd du -> lo
        float2 t1 = g_D[n][br][2*p+2][x];    // even du -> hi
        dcx2[p] = pk2( 2.f*t0.x,  2.f*t1.x);
        dcy2[p] = pk2(-2.f*t0.y, -2.f*t1.y);
    }
    __syncthreads();

    const size_t plane = (size_t)NB * HH * WW;
    const size_t base  = (size_t)n * HH * WW;
    for (int yy = 0; yy < 16; yy++) {
        int yp = warp*16 + yy;
        int y  = yq*128 + yp;                // in [0,512)
        unsigned long long acc = pk2(0.f, D0);
        #pragma unroll
        for (int p = 0; p < 17; p++) {
            acc = fma2(dcx2[p], twx[yp][p], acc);
            acc = fma2(dcy2[p], twy[yp][p], acc);
        }
        float Ilo, Ihi;
        upk2(acc, Ilo, Ihi);
        float Ia = Ihi + Ilo;                // I(y)
        float Ib = Ihi - Ilo;                // I(y+512)
        size_t oa = base + (size_t)y * WW + x;
        size_t ob = oa + (size_t)512 * WW;
        if (br == 0) {
            float IamX = 1.0404f * Ia, IbmX = 1.0404f * Ib;
            out[oa]           = 1.f/(1.f + expf(-50.f*(Ia   - 0.225f)));
            out[ob]           = 1.f/(1.f + expf(-50.f*(Ib   - 0.225f)));
            out[2*plane + oa] = 1.f/(1.f + expf(-50.f*(IamX - 0.225f)));
            out[2*plane + ob] = 1.f/(1.f + expf(-50.f*(IbmX - 0.225f)));
            out[3*plane + oa] = Ia;
            out[3*plane + ob] = Ib;
            out[5*plane + oa] = IamX;
            out[5*plane + ob] = IbmX;
        } else {
            float IamN = 0.9604f * Ia, IbmN = 0.9604f * Ib;
            out[plane   + oa] = 1.f/(1.f + expf(-50.f*(IamN - 0.225f)));
            out[plane   + ob] = 1.f/(1.f + expf(-50.f*(IbmN - 0.225f)));
            out[4*plane + oa] = IamN;
            out[4*plane + ob] = IbmN;
        }
    }
}

// ---------------- launch ----------------
extern "C" void kernel_launch(void* const* d_in, const int* in_sizes, int n_in,
                              void* d_out, int out_size) {
    const float* mask = (const float*)d_in[0];
    const float* fr   = (const float*)d_in[1];
    const float* fi   = (const float*)d_in[2];
    const float* dr   = (const float*)d_in[3];
    const float* di   = (const float*)d_in[4];
    const float* fs   = (const float*)d_in[5];
    const float* ds   = (const float*)d_in[6];
    float* out = (float*)d_out;

    k_table  <<<1, 1024>>>();
    k_rowdft <<<dim3(256, NB), 256>>>(mask);
    k_coldft <<<dim3(KD, NB), 256>>>();
    k_R128   <<<dim3(KK, 8), 128>>>(fr, fi, dr, di);
    k_D1s    <<<dim3(8, 8), 128>>>(fs, ds);
    k_G2     <<<dim3(KD, 4), 128>>>();
    k_Dsyn   <<<dim3(KD, 4), 256>>>();
    k_final  <<<dim3(32, 4, 4), 256>>>(out);
}

// round 10
// speedup vs baseline: 1.0973x; 1.0973x over previous
#include <cuda_runtime.h>
#include <math.h>

#define HH 1024
#define WW 1024
#define NB 2
#define KK 24   // number of SOCS kernels
#define KD 35   // kernel spatial size / cropped spectrum size
#define FC 17   // center offset: frequency f = index - 17
#define UG 3    // u2-pairs per k_R block
#define NUG 6   // u2 groups (6*3 = 18 u-pairs)

// ---------------- scratch (static __device__, no allocation) ----------------
__device__ float2 g_cs[1024];                 // e^{+2pi i t/1024}
__device__ float2 g_T[NB][KD][HH];            // row DFT, transposed (j2-major)
__device__ float2 g_spec[NB][KD][KD];         // cropped spectrum (1/(H*W) folded)
__device__ float2 g_R[NB][2][KK][KD][WW];     // row-synthesized fields
__device__ float2 g_Dpart[8][NB][2][KD][WW];  // per-k-group partial Gram

// ---------------- f32x2 packed helpers (Blackwell) ----------------
__device__ __forceinline__ unsigned long long pk2(float lo, float hi) {
    unsigned long long r;
    asm("mov.b64 %0, {%1, %2};" : "=l"(r) : "f"(lo), "f"(hi));
    return r;
}
__device__ __forceinline__ unsigned long long fma2(unsigned long long a, unsigned long long b, unsigned long long c) {
    unsigned long long d;
    asm("fma.rn.f32x2 %0, %1, %2, %3;" : "=l"(d) : "l"(a), "l"(b), "l"(c));
    return d;
}
__device__ __forceinline__ unsigned long long add2(unsigned long long a, unsigned long long b) {
    unsigned long long d;
    asm("add.rn.f32x2 %0, %1, %2;" : "=l"(d) : "l"(a), "l"(b));
    return d;
}
__device__ __forceinline__ unsigned long long sub2(unsigned long long a, unsigned long long b) {
    unsigned long long d;
    asm("{\n\t.reg .b64 nb;\n\tmul.rn.f32x2 nb, %2, %3;\n\tadd.rn.f32x2 %0, %1, nb;\n\t}"
        : "=l"(d) : "l"(a), "l"(b), "l"(0xBF800000BF800000ull));  // a + b*(-1,-1)
    return d;
}
__device__ __forceinline__ void upk2(unsigned long long v, float& lo, float& hi) {
    asm("mov.b64 {%0, %1}, %2;" : "=f"(lo), "=f"(hi) : "l"(v));
}

// exact twiddle: e^{+2pi i t/1024} for integer t (can be negative)
__device__ __forceinline__ float2 twd(int t) {
    float s, c;
    sincospif((float)(t & 1023) / 512.0f, &s, &c);
    return make_float2(c, s);
}

// ---------------- stage 1: fused avepool3+sigmoid + row DFT (+ table block) ----------------
__global__ void __launch_bounds__(256) k_rowdft(const float* __restrict__ mask) {
    int yb = blockIdx.x;
    int n  = blockIdx.y;
    int tid = threadIdx.x;
    if (yb == 256) {                          // twiddle-table block (for later kernels)
        if (n == 0) {
            for (int t = tid; t < 1024; t += 256) {
                float s, c;
                sincospif((float)t / 512.0f, &s, &c);
                g_cs[t] = make_float2(c, s);
            }
        }
        return;
    }
    __shared__ float raw[6][WW];
    __shared__ float m_s[4][WW];
    const float* base = mask + (size_t)n * HH * WW;
    #pragma unroll
    for (int j = 0; j < 6; j++) {
        int gy = yb*4 - 1 + j;
        for (int x = tid; x < WW; x += 256)
            raw[j][x] = (gy >= 0 && gy < HH) ? base[(size_t)gy * WW + x] : 0.f;
    }
    __syncthreads();
    for (int x = tid; x < WW; x += 256) {
        float r0 = raw[0][x], r1 = raw[1][x], r2 = raw[2][x];
        float r3 = raw[3][x], r4 = raw[4][x], r5 = raw[5][x];
        raw[0][x] = r0 + r1 + r2;
        raw[1][x] = r1 + r2 + r3;
        raw[2][x] = r2 + r3 + r4;
        raw[3][x] = r3 + r4 + r5;
    }
    __syncthreads();
    for (int x = tid; x < WW; x += 256) {
        #pragma unroll
        for (int yy = 0; yy < 4; yy++) {
            float s = raw[yy][x];
            if (x > 0)    s += raw[yy][x-1];
            if (x < WW-1) s += raw[yy][x+1];
            float p = s * (1.0f/9.0f);
            m_s[yy][x] = 1.0f / (1.0f + expf(-4.0f * (p - 0.5f)));
        }
    }
    __syncthreads();
    int warp = tid >> 5, lane = tid & 31;
    for (int j2 = warp; j2 < KD; j2 += 8) {
        int a = FC - j2;                      // e^{-2pi i (j2-17) x/N} = e^{+2pi i a x/N}
        float2 t  = twd(a * lane);
        float2 st = twd(a * 32);              // warp-uniform step
        unsigned long long acc[4] = {0ull, 0ull, 0ull, 0ull};
        for (int i = 0; i < 32; i++) {
            int x = lane + 32*i;
            unsigned long long t2 = pk2(t.x, t.y);
            #pragma unroll
            for (int yy = 0; yy < 4; yy++) {
                float mv = m_s[yy][x];
                acc[yy] = fma2(pk2(mv, mv), t2, acc[yy]);
            }
            float tx = t.x*st.x - t.y*st.y;
            float ty = t.x*st.y + t.y*st.x;
            t = make_float2(tx, ty);
        }
        #pragma unroll
        for (int yy = 0; yy < 4; yy++) {
            float ar, ai;
            upk2(acc[yy], ar, ai);
            for (int o = 16; o; o >>= 1) {
                ar += __shfl_xor_sync(0xffffffffu, ar, o);
                ai += __shfl_xor_sync(0xffffffffu, ai, o);
            }
            if (lane == 0) g_T[n][j2][yb*4 + yy] = make_float2(ar, ai);
        }
    }
}

// ---------------- stage 2: column DFT, one block per (j2,n) ----------------
__global__ void __launch_bounds__(256) k_coldft() {
    __shared__ float2 Ts[HH];
    int j2 = blockIdx.x, n = blockIdx.y;
    int tid = threadIdx.x;
    for (int i = tid; i < HH; i += 256) Ts[i] = g_T[n][j2][i];
    __syncthreads();
    int warp = tid >> 5, lane = tid & 31;
    const float norm = 1.0f / (1024.0f * 1024.0f);
    for (int j1 = warp; j1 < KD; j1 += 8) {
        int a = FC - j1;
        float2 t  = g_cs[(a * lane) & 1023];
        float2 st = g_cs[(a * 32)   & 1023];
        float ar = 0.f, ai = 0.f;
        for (int i = 0; i < 32; i++) {
            float2 T = Ts[lane + 32*i];
            ar += T.x*t.x - T.y*t.y;
            ai += T.x*t.y + T.y*t.x;
            float tx = t.x*st.x - t.y*st.y;
            float ty = t.x*st.y + t.y*st.x;
            t = make_float2(tx, ty);
        }
        for (int o = 16; o; o >>= 1) {
            ar += __shfl_xor_sync(0xffffffffu, ar, o);
            ai += __shfl_xor_sync(0xffffffffu, ai, o);
        }
        if (lane == 0) g_spec[n][j1][j2] = make_float2(ar * norm, ai * norm);
    }
}

// ---------------- stage 3: radix-4 row synthesis ----------------
// R[u, x0+256q] = sum_c i^{cq} * A_c(u,x0), A_c = sum_{v=c mod 4} B[u,v] e^{+2pi i v x0/1024}
__global__ void __launch_bounds__(256) k_R(const float* __restrict__ fr, const float* __restrict__ fi,
                                           const float* __restrict__ dr, const float* __restrict__ di) {
    __shared__ float4 Bs[KD][UG + 1];         // (b0x, b1x, b0y, b1y) per (v, u2)
    int k = blockIdx.x;
    int z = blockIdx.y;                       // ug(6) * nbr(4)
    int ug = z % NUG; int nbr = z / NUG;
    int n = nbr >> 1, br = nbr & 1;
    int u2base = ug * UG;
    int tid = threadIdx.x;
    const float* krp = (br == 0) ? fr : dr;
    const float* kip = (br == 0) ? fi : di;
    for (int i = tid; i < KD*UG; i += 256) {
        int uu = i / KD, v = i % KD;
        int u0 = 2*(u2base + uu), u1 = u0 + 1;
        float2 A0 = g_spec[n][u0][v];
        float Kr = krp[(k*KD + u0)*KD + v];
        float Ki = kip[(k*KD + u0)*KD + v];
        float b0x = A0.x*Kr - A0.y*Ki, b0y = A0.x*Ki + A0.y*Kr;
        float b1x = 0.f, b1y = 0.f;
        if (u1 < KD) {
            float2 A1 = g_spec[n][u1][v];
            float Kr1 = krp[(k*KD + u1)*KD + v];
            float Ki1 = kip[(k*KD + u1)*KD + v];
            b1x = A1.x*Kr1 - A1.y*Ki1; b1y = A1.x*Ki1 + A1.y*Kr1;
        }
        Bs[v][uu] = make_float4(b0x, b1x, b0y, b1y);
    }
    __syncthreads();
    int x0 = tid;                             // 0..255
    unsigned long long aR[4][UG], aI[4][UG];
    #pragma unroll
    for (int c = 0; c < 4; c++)
        #pragma unroll
        for (int uu = 0; uu < UG; uu++) { aR[c][uu] = 0ull; aI[c][uu] = 0ull; }
    float2 w = g_cs[x0];
    float2 t = make_float2(1.f, 0.f);
    #pragma unroll
    for (int v = 0; v < KD; v++) {
        const int c = v & 3;
        unsigned long long pxx = pk2(t.x,  t.x);
        unsigned long long pyy = pk2(t.y,  t.y);
        unsigned long long nyy = pk2(-t.y, -t.y);
        #pragma unroll
        for (int uu = 0; uu < UG; uu++) {
            float4 b = Bs[v][uu];
            unsigned long long bx = pk2(b.x, b.y);
            unsigned long long by = pk2(b.z, b.w);
            aR[c][uu] = fma2(bx, pxx, aR[c][uu]);
            aR[c][uu] = fma2(by, nyy, aR[c][uu]);
            aI[c][uu] = fma2(bx, pyy, aI[c][uu]);
            aI[c][uu] = fma2(by, pxx, aI[c][uu]);
        }
        float tx = t.x*w.x - t.y*w.y;         // t *= w (exact-table step)
        float ty = t.x*w.y + t.y*w.x;
        t = make_float2(tx, ty);
    }
    #pragma unroll
    for (int uu = 0; uu < UG; uu++) {
        int u0 = 2*(u2base + uu);
        unsigned long long PR = add2(aR[0][uu], aR[2][uu]);
        unsigned long long QR = add2(aR[1][uu], aR[3][uu]);
        unsigned long long MR = sub2(aR[0][uu], aR[2][uu]);
        unsigned long long DR = sub2(aR[1][uu], aR[3][uu]);
        unsigned long long PI = add2(aI[0][uu], aI[2][uu]);
        unsigned long long QI = add2(aI[1][uu], aI[3][uu]);
        unsigned long long MI = sub2(aI[0][uu], aI[2][uu]);
        unsigned long long DI = sub2(aI[1][uu], aI[3][uu]);
        unsigned long long Rq[4], Iq[4];
        Rq[0] = add2(PR, QR); Iq[0] = add2(PI, QI);
        Rq[2] = sub2(PR, QR); Iq[2] = sub2(PI, QI);
        Rq[1] = sub2(MR, DI); Iq[1] = add2(MI, DR);
        Rq[3] = add2(MR, DI); Iq[3] = sub2(MI, DR);
        #pragma unroll
        for (int q = 0; q < 4; q++) {
            float r0, r1, i0, i1;
            upk2(Rq[q], r0, r1);
            upk2(Iq[q], i0, i1);
            int x = x0 + 256*q;
            g_R[n][br][k][u0][x] = make_float2(r0, i0);
            if (u0 + 1 < KD) g_R[n][br][k][u0+1][x] = make_float2(r1, i1);
        }
    }
}

// ---------------- stage 4: partial Gram (f32x2 packed) ----------------
template <int DU0, int DW>
__device__ __forceinline__ void gram_half(int n, int br, int kg, int x, const float* sp) {
    unsigned long long acc[DW];
    #pragma unroll
    for (int j = 0; j < DW; j++) acc[j] = 0ull;
    #pragma unroll 1
    for (int kk = 0; kk < 3; kk++) {
        int k = kg*3 + kk;
        float s = sp[k];
        float2 Ru[KD];
        #pragma unroll
        for (int u = 0; u < KD; u++) Ru[u] = g_R[n][br][k][u][x];
        #pragma unroll
        for (int u = 0; u < KD; u++) {
            float ax = s * Ru[u].x;
            float ay = s * Ru[u].y;
            unsigned long long axy  = pk2(ax, ay);
            unsigned long long ayxn = pk2(ay, -ax);
            #pragma unroll
            for (int j = 0; j < DW; j++) {
                if (DU0 + j <= u) {
                    float2 b = Ru[u - DU0 - j];
                    acc[j] = fma2(axy,  pk2(b.x, b.x), acc[j]);
                    acc[j] = fma2(ayxn, pk2(b.y, b.y), acc[j]);
                }
            }
        }
    }
    #pragma unroll
    for (int j = 0; j < DW; j++) {
        float rx, ry;
        upk2(acc[j], rx, ry);
        g_Dpart[kg][n][br][DU0 + j][x] = make_float2(rx, ry);
    }
}

__global__ void __launch_bounds__(128) k_D1(const float* __restrict__ fs, const float* __restrict__ ds) {
    int xt  = blockIdx.x;                    // 8 tiles of 128 x
    int kg  = blockIdx.y;                    // 8 k-groups of 3
    int z   = blockIdx.z;                    // nbr(4) * half(2)
    int nbr = z >> 1, half = z & 1;
    int n = nbr >> 1, br = nbr & 1;
    int x = xt*128 + threadIdx.x;
    const float* sp = (br == 0) ? fs : ds;
    if (half == 0) gram_half<0, 18>(n, br, kg, x, sp);
    else           gram_half<18, 17>(n, br, kg, x, sp);
}

// ---------------- stage 5: reduce partials + synthesis (radix-2 in y) + outputs ----------------
__global__ void __launch_bounds__(256) k_final(float* __restrict__ out) {
    __shared__ unsigned long long twx[128][17];
    __shared__ unsigned long long twy[128][17];
    __shared__ float2 Ds[KD][32];             // reduced D[du] for this block's 32 x
    int xs = blockIdx.x;                     // 32-wide x strip
    int yq = blockIdx.y;                     // 0..3 (128 rows each, y in [0,512))
    int bz = blockIdx.z;                     // n(2) x br(2)
    int n = bz >> 1, br = bz & 1;
    int tid = threadIdx.x;
    // reduce k-group partials for this x strip (fold of old k_D2)
    for (int idx = tid; idx < KD*32; idx += 256) {
        int du = idx >> 5, xl = idx & 31;
        int x = xs*32 + xl;
        float sx = 0.f, sy = 0.f;
        #pragma unroll
        for (int kg = 0; kg < 8; kg++) {
            float2 t = g_Dpart[kg][n][br][du][x];
            sx += t.x; sy += t.y;
        }
        Ds[du][xl] = make_float2(sx, sy);
    }
    for (int idx = tid; idx < 128*17; idx += 256) {
        int yp = idx / 17, p = idx % 17;
        int y = yq*128 + yp;
        float2 c0 = g_cs[((2*p+1) * y) & 1023];
        float2 c1 = g_cs[((2*p+2) * y) & 1023];
        twx[yp][p] = pk2(c0.x, c1.x);
        twy[yp][p] = pk2(c0.y, c1.y);
    }
    __syncthreads();
    int lane = tid & 31, warp = tid >> 5;
    int x = xs*32 + lane;
    float D0 = Ds[0][lane].x;                // D[0] is real
    unsigned long long dcx2[17], dcy2[17];
    #pragma unroll
    for (int p = 0; p < 17; p++) {
        float2 t0 = Ds[2*p+1][lane];         // odd du -> lo
        float2 t1 = Ds[2*p+2][lane];         // even du -> hi
        dcx2[p] = pk2( 2.f*t0.x,  2.f*t1.x);
        dcy2[p] = pk2(-2.f*t0.y, -2.f*t1.y);
    }

    const size_t plane = (size_t)NB * HH * WW;
    const size_t base  = (size_t)n * HH * WW;
    for (int yy = 0; yy < 16; yy++) {
        int yp = warp*16 + yy;
        int y  = yq*128 + yp;                // in [0,512)
        unsigned long long acc = pk2(0.f, D0);
        #pragma unroll
        for (int p = 0; p < 17; p++) {
            acc = fma2(dcx2[p], twx[yp][p], acc);
            acc = fma2(dcy2[p], twy[yp][p], acc);
        }
        float Ilo, Ihi;
        upk2(acc, Ilo, Ihi);
        float Ia = Ihi + Ilo;                // I(y)
        float Ib = Ihi - Ilo;                // I(y+512)
        size_t oa = base + (size_t)y * WW + x;
        size_t ob = oa + (size_t)512 * WW;
        if (br == 0) {
            float IamX = 1.0404f * Ia, IbmX = 1.0404f * Ib;
            out[oa]           = 1.f/(1.f + expf(-50.f*(Ia   - 0.225f)));
            out[ob]           = 1.f/(1.f + expf(-50.f*(Ib   - 0.225f)));
            out[2*plane + oa] = 1.f/(1.f + expf(-50.f*(IamX - 0.225f)));
            out[2*plane + ob] = 1.f/(1.f + expf(-50.f*(IbmX - 0.225f)));
            out[3*plane + oa] = Ia;
            out[3*plane + ob] = Ib;
            out[5*plane + oa] = IamX;
            out[5*plane + ob] = IbmX;
        } else {
            float IamN = 0.9604f * Ia, IbmN = 0.9604f * Ib;
            out[plane   + oa] = 1.f/(1.f + expf(-50.f*(IamN - 0.225f)));
            out[plane   + ob] = 1.f/(1.f + expf(-50.f*(IbmN - 0.225f)));
            out[4*plane + oa] = IamN;
            out[4*plane + ob] = IbmN;
        }
    }
}

// ---------------- launch (5 kernels) ----------------
extern "C" void kernel_launch(void* const* d_in, const int* in_sizes, int n_in,
                              void* d_out, int out_size) {
    const float* mask = (const float*)d_in[0];
    const float* fr   = (const float*)d_in[1];
    const float* fi   = (const float*)d_in[2];
    const float* dr   = (const float*)d_in[3];
    const float* di   = (const float*)d_in[4];
    const float* fs   = (const float*)d_in[5];
    const float* ds   = (const float*)d_in[6];
    float* out = (float*)d_out;

    k_rowdft <<<dim3(257, NB), 256>>>(mask);
    k_coldft <<<dim3(KD, NB), 256>>>();
    k_R      <<<dim3(KK, NUG*4), 256>>>(fr, fi, dr, di);
    k_D1     <<<dim3(8, 8, 8), 128>>>(fs, ds);
    k_final  <<<dim3(32, 4, 4), 256>>>(out);
}